// round 13
// baseline (speedup 1.0000x reference)
#include <cuda_runtime.h>

#define BB 16
#define NP 4000
#define TK 512            // sorted candidate capacity (pow2)
#define NCHUNK (TK/32)    // 16
#define KSEL 384          // target top-K for threshold selection
#define DD 1024
#define NROWS (BB*NP)
#define CLIPV 4.135166556742356f   // log(1000/16)
#define FULLM 0xffffffffu

__device__ float g_scores[NROWS];
__device__ int g_hist[BB * 256];   // zero-init; re-zeroed by nms each call

// ---------------------------------------------------------------------------
// Kernel 1: fused head. Per-warp private cp.async pipeline, 2-stage ring,
// 8 warps x 8 rows (weight-read amortization). 2 blocks/SM (88 KB smem).
// ---------------------------------------------------------------------------
__global__ __launch_bounds__(256, 2) void head_kernel(
    const float* __restrict__ feats, const float* __restrict__ proposals,
    const float* __restrict__ W_cls, const float* __restrict__ b_cls,
    const float* __restrict__ W_box, const float* __restrict__ b_box,
    float* __restrict__ out)
{
    extern __shared__ float sm[];
    float4* wS   = reinterpret_cast<float4*>(sm);   // 6*256 float4 = 24 KB
    float*  fS   = sm + 6 * DD;                     // 8 warps * 2048 floats

    const int tid  = threadIdx.x;
    const int warp = tid >> 5;
    const int lane = tid & 31;
    const int grow0 = blockIdx.x * 64 + warp * 8;   // this warp's first row

    float* wbuf = fS + warp * (2 * 1024);           // 2 stages x 1024 floats
    const unsigned sb = (unsigned)__cvta_generic_to_shared(wbuf);

    // issue stage st loading column chunk j (cols [j*128, j*128+128)) x 8 rows
    auto issue_stage = [&](int st, int j) {
        #pragma unroll
        for (int r = 0; r < 8; r++) {
            const float* gsrc = feats + (size_t)(grow0 + r) * DD + j * 128 + 4 * lane;
            unsigned dst = sb + st * 4096 + r * 512 + 16 * lane;
            asm volatile("cp.async.cg.shared.global [%0], [%1], 16;\n"
                         :: "r"(dst), "l"(gsrc));
        }
        asm volatile("cp.async.commit_group;\n");
    };

    issue_stage(0, 0);
    issue_stage(1, 1);

    // stage weights (block-cooperative): rows 0-1 W_cls, rows 2-5 W_box[4..7]
    for (int i = tid; i < 6 * 256; i += 256) {
        int c = i >> 8, e = i & 255;
        const float* src = (c < 2) ? (W_cls + c * DD) : (W_box + (c + 2) * DD);
        wS[i] = reinterpret_cast<const float4*>(src)[e];
    }
    __syncthreads();

    float acc[8][6];
    #pragma unroll
    for (int r = 0; r < 8; r++)
        #pragma unroll
        for (int c = 0; c < 6; c++) acc[r][c] = 0.f;

    #pragma unroll
    for (int j = 0; j < 8; j++) {
        if (j < 7) asm volatile("cp.async.wait_group 1;\n");
        else       asm volatile("cp.async.wait_group 0;\n");

        const float* fb = wbuf + (j & 1) * 1024;
        float4 w[6];
        #pragma unroll
        for (int c = 0; c < 6; c++) w[c] = wS[c * 256 + j * 32 + lane];
        #pragma unroll
        for (int r = 0; r < 8; r++) {
            float4 fr = *reinterpret_cast<const float4*>(fb + r * 128 + 4 * lane);
            #pragma unroll
            for (int c = 0; c < 6; c++)
                acc[r][c] += fr.x * w[c].x + fr.y * w[c].y +
                             fr.z * w[c].z + fr.w * w[c].w;
        }
        if (j < 6) issue_stage(j & 1, j + 2);   // reuse buffer after compute
    }

    #pragma unroll
    for (int r = 0; r < 8; r++)
        #pragma unroll
        for (int c = 0; c < 6; c++)
            #pragma unroll
            for (int s = 16; s > 0; s >>= 1)
                acc[r][c] += __shfl_xor_sync(FULLM, acc[r][c], s);

    if (lane < 8) {
        float v0 = 0.f, v1 = 0.f, v2 = 0.f, v3 = 0.f, v4 = 0.f, v5 = 0.f;
        #pragma unroll
        for (int r = 0; r < 8; r++)
            if (lane == r) {
                v0 = acc[r][0]; v1 = acc[r][1]; v2 = acc[r][2];
                v3 = acc[r][3]; v4 = acc[r][4]; v5 = acc[r][5];
            }
        const int row = grow0 + lane;

        float l0 = v0 + b_cls[0];
        float l1 = v1 + b_cls[1];
        float score = 1.f / (1.f + expf(l0 - l1));

        float dx = (v2 + b_box[4]) / 10.0f;
        float dy = (v3 + b_box[5]) / 10.0f;
        float dw = fminf((v4 + b_box[6]) / 5.0f, CLIPV);
        float dh = fminf((v5 + b_box[7]) / 5.0f, CLIPV);

        float4 p = reinterpret_cast<const float4*>(proposals)[row];
        float w  = p.z - p.x;
        float h  = p.w - p.y;
        float cx = p.x + 0.5f * w;
        float cy = p.y + 0.5f * h;
        float pcx = dx * w + cx;
        float pcy = dy * h + cy;
        float pw  = expf(dw) * w;
        float ph  = expf(dh) * h;

        float x1 = fminf(fmaxf(pcx - 0.5f * pw, 0.f), 800.f);
        float y1 = fminf(fmaxf(pcy - 0.5f * ph, 0.f), 800.f);
        float x2 = fminf(fmaxf(pcx + 0.5f * pw, 0.f), 800.f);
        float y2 = fminf(fmaxf(pcy + 0.5f * ph, 0.f), 800.f);

        float* o = out + (size_t)row * 5;
        o[0] = x1; o[1] = y1; o[2] = x2; o[3] = y2;
        o[4] = 0.f;                       // default: not kept

        if (score > 0.25f) {
            g_scores[row] = score;
            unsigned bits = __float_as_uint(score);
            int bin = min(max((int)((bits - 0x3E800000u) >> 16), 0), 255);
            atomicAdd(&g_hist[(row / NP) * 256 + bin], 1);
        } else {
            g_scores[row] = 0.f;
        }
    }
}

// ---------------------------------------------------------------------------
// Kernel 2: fused NMS (unchanged from R10/R11 best). One block per batch.
// ---------------------------------------------------------------------------
__global__ __launch_bounds__(1024) void nms_kernel(float* __restrict__ out)
{
    __shared__ unsigned long long KEY[TK];
    __shared__ float BX1[TK], BY1[TK], BX2[TK], BY2[TK], BAR_[TK], BSC[TK];
    __shared__ int   BIDX[TK];
    __shared__ unsigned MYCOL[TK];
    __shared__ unsigned ALIVE0[NCHUNK];
    __shared__ int   CONF[32];
    __shared__ int   ACC[128];
    __shared__ unsigned tbits_s;
    __shared__ int ccount, npick_s, done_s;

    const int b = blockIdx.x;
    const int t = threadIdx.x;
    float* ob = out + (size_t)b * NP * 5;
    const float4* gs4 = reinterpret_cast<const float4*>(g_scores + b * NP);

    if (t == 0) { ccount = 0; npick_s = 0; done_s = 0; }

    // ---- threshold from histogram (warp 0, register suffix scan) ----
    if (t < 32) {
        int h[8];
        #pragma unroll
        for (int q = 0; q < 8; q++)
            h[q] = g_hist[b * 256 + t * 8 + q];
        #pragma unroll
        for (int q = 6; q >= 0; q--) h[q] += h[q + 1];
        int lanetot = h[0];
        int suf = lanetot;
        #pragma unroll
        for (int s = 1; s < 32; s <<= 1) {
            int o = __shfl_down_sync(FULLM, suf, s);
            if (t + s < 32) suf += o;
        }
        int excl = suf - lanetot;
        unsigned lm = __ballot_sync(FULLM, (h[0] + excl) >= KSEL);
        if (lm == 0u) {
            if (t == 0) tbits_s = 0x3E800000u;
        } else {
            int hl = 31 - __clz(lm);
            if (t == hl) {
                int bq = 0;
                #pragma unroll
                for (int q = 1; q < 8; q++)
                    if (h[q] + excl >= KSEL) bq = q;
                tbits_s = 0x3E800000u + ((unsigned)(t * 8 + bq) << 16);
            }
        }
    }
    __syncthreads();
    const unsigned tbits = tbits_s;

    if (t < 256) g_hist[b * 256 + t] = 0;    // reset for next launch

    // ---- compact candidates ----
    if (t < NP / 4) {
        float4 sv = gs4[t];
        const float* s = &sv.x;
        unsigned bits[4];
        int cnt = 0;
        #pragma unroll
        for (int q = 0; q < 4; q++) {
            bits[q] = __float_as_uint(s[q]);
            if (s[q] > 0.f && bits[q] >= tbits) cnt++;
        }
        if (cnt) {
            int slot = atomicAdd(&ccount, cnt);
            #pragma unroll
            for (int q = 0; q < 4; q++) {
                if (s[q] > 0.f && bits[q] >= tbits && slot < TK) {
                    int n = t * 4 + q;
                    KEY[slot++] = ((unsigned long long)bits[q] << 32)
                                | (unsigned long long)(4095 - n);
                }
            }
        }
    }
    __syncthreads();
    const int C = min(ccount, TK);
    if (t >= C && t < TK) KEY[t] = 0ull;
    __syncthreads();

    // ---- bitonic sort descending, 512 keys ----
    if (t < TK) {
        unsigned long long e = KEY[t];
        #pragma unroll
        for (int k = 2; k <= 32; k <<= 1)
            #pragma unroll
            for (int j = k >> 1; j > 0; j >>= 1) {
                unsigned long long p = __shfl_xor_sync(FULLM, e, j);
                bool mx = ((t & k) == 0) == ((t & j) == 0);
                e = mx ? (e > p ? e : p) : (e < p ? e : p);
            }
        KEY[t] = e;
    }
    __syncthreads();

    for (int k = 64; k <= TK; k <<= 1) {
        for (int j = k >> 1; j >= 32; j >>= 1) {
            if (t < TK) {
                int ixj = t ^ j;
                if (ixj > t) {
                    unsigned long long a = KEY[t];
                    unsigned long long c = KEY[ixj];
                    bool swap = ((t & k) == 0) ? (a < c) : (a > c);
                    if (swap) { KEY[t] = c; KEY[ixj] = a; }
                }
            }
            __syncthreads();
        }
        if (t < TK) {
            unsigned long long e = KEY[t];
            bool dir = ((t & k) == 0);
            #pragma unroll
            for (int j = 16; j > 0; j >>= 1) {
                unsigned long long p = __shfl_xor_sync(FULLM, e, j);
                bool mx = dir == ((t & j) == 0);
                e = mx ? (e > p ? e : p) : (e < p ? e : p);
            }
            KEY[t] = e;
        }
        __syncthreads();
    }

    // ---- parallel candidate prep + intra-chunk pairwise masks ----
    {
        const int w = t >> 5, lane = t & 31;
        if (w < NCHUNK) {
            const int slot = w * 32 + lane;
            unsigned long long key = KEY[slot];
            float sc = __uint_as_float((unsigned)(key >> 32));
            int   idx = 4095 - (int)(key & 0xFFFull);
            float x1 = 0.f, y1 = 0.f, x2 = 0.f, y2 = 0.f;
            if (sc > 0.f) {
                x1 = __ldg(&ob[idx * 5 + 0]); y1 = __ldg(&ob[idx * 5 + 1]);
                x2 = __ldg(&ob[idx * 5 + 2]); y2 = __ldg(&ob[idx * 5 + 3]);
            }
            float ar = fmaxf(x2 - x1, 0.f) * fmaxf(y2 - y1, 0.f);
            BX1[slot] = x1; BY1[slot] = y1;
            BX2[slot] = x2; BY2[slot] = y2;
            BAR_[slot] = ar; BSC[slot] = sc; BIDX[slot] = idx;
            unsigned am = __ballot_sync(FULLM, sc > 0.f);
            if (lane == 0) ALIVE0[w] = am;

            unsigned conf = 0;
            #pragma unroll 4
            for (int j = 0; j < 32; j++) {
                float cx1 = __shfl_sync(FULLM, x1, j);
                float cy1 = __shfl_sync(FULLM, y1, j);
                float cx2 = __shfl_sync(FULLM, x2, j);
                float cy2 = __shfl_sync(FULLM, y2, j);
                float ca  = fmaxf(cx2 - cx1, 0.f) * fmaxf(cy2 - cy1, 0.f);
                float ix1 = fmaxf(cx1, x1);
                float iy1 = fmaxf(cy1, y1);
                float ix2 = fminf(cx2, x2);
                float iy2 = fminf(cy2, y2);
                float inter = fmaxf(ix2 - ix1, 0.f) * fmaxf(iy2 - iy1, 0.f);
                float denom = ca + ar - inter + 1e-9f;
                if (inter > 0.5f * denom) conf |= (1u << j);
            }
            unsigned mycol = 0;
            #pragma unroll
            for (int j = 0; j < 32; j++) {
                unsigned bcol = __ballot_sync(FULLM, (conf >> j) & 1u);
                if (lane == j) mycol = bcol;
            }
            MYCOL[slot] = mycol;
        }
    }
    __syncthreads();

    // ---- chunk loop: block-parallel accepted-test + uniform resolve ----
    for (int chunk = 0; chunk < NCHUNK; chunk++) {
        if (done_s) break;

        {
            const int wi = t >> 5, lane = t & 31;
            const int cslot = chunk * 32 + wi;
            const int np = npick_s;
            float cx1 = BX1[cslot], cy1 = BY1[cslot];
            float cx2 = BX2[cslot], cy2 = BY2[cslot];
            float car = BAR_[cslot];
            bool conflict = false;
            #pragma unroll
            for (int s2 = 0; s2 < 4; s2++) {
                int a = s2 * 32 + lane;
                if (a < np) {
                    int jj = ACC[a];
                    float ix1 = fmaxf(BX1[jj], cx1);
                    float iy1 = fmaxf(BY1[jj], cy1);
                    float ix2 = fminf(BX2[jj], cx2);
                    float iy2 = fminf(BY2[jj], cy2);
                    float inter = fmaxf(ix2 - ix1, 0.f) * fmaxf(iy2 - iy1, 0.f);
                    float denom = BAR_[jj] + car - inter + 1e-9f;
                    if (inter > 0.5f * denom) conflict = true;
                }
            }
            unsigned cb = __ballot_sync(FULLM, conflict);
            if (lane == 0) CONF[wi] = (cb != 0u) ? 1 : 0;
        }
        __syncthreads();

        if (t < 32) {
            const int lane = t;
            unsigned a0 = ALIVE0[chunk];
            if ((a0 & 1u) == 0u) {
                if (lane == 0) done_s = 1;
            } else {
                bool cf = CONF[lane] != 0;
                unsigned alive = a0 & ~__ballot_sync(FULLM, cf);
                int np = npick_s;
                unsigned rem = alive, picked = 0;
                while (rem && np < 100) {
                    int kk = __ffs(rem) - 1;
                    picked |= (1u << kk);
                    np++;
                    unsigned kills = MYCOL[chunk * 32 + kk];
                    rem &= ~kills;
                    rem &= ~(1u << kk);
                }
                if ((picked >> lane) & 1u) {
                    int pos = npick_s + __popc(picked & ((1u << lane) - 1u));
                    int cslot = chunk * 32 + lane;
                    ACC[pos] = cslot;
                    ob[BIDX[cslot] * 5 + 4] = BSC[cslot];
                }
                if (lane == 0) {
                    npick_s = np;
                    if (np >= 100) done_s = 1;
                }
            }
        }
        __syncthreads();
    }
}

extern "C" void kernel_launch(void* const* d_in, const int* in_sizes, int n_in,
                              void* d_out, int out_size)
{
    const float* feats     = (const float*)d_in[0];
    const float* proposals = (const float*)d_in[1];
    const float* W_cls     = (const float*)d_in[2];
    const float* b_cls     = (const float*)d_in[3];
    const float* W_box     = (const float*)d_in[4];
    const float* b_box     = (const float*)d_in[5];
    float* out = (float*)d_out;

    const int head_smem = (6 * DD + 8 * 2 * 1024) * (int)sizeof(float); // 88 KB
    cudaFuncSetAttribute(head_kernel,
                         cudaFuncAttributeMaxDynamicSharedMemorySize,
                         head_smem);
    head_kernel<<<NROWS / 64, 256, head_smem>>>(feats, proposals, W_cls, b_cls,
                                                W_box, b_box, out);
    nms_kernel<<<BB, 1024>>>(out);
}

// round 14
// speedup vs baseline: 1.0368x; 1.0368x over previous
#include <cuda_runtime.h>

#define BB 16
#define NP 4000
#define TK 512            // sorted candidate capacity (pow2)
#define NCHUNK (TK/32)    // 16
#define KSEL 384          // target top-K for threshold selection
#define DD 1024
#define NROWS (BB*NP)
#define CLIPV 4.135166556742356f   // log(1000/16)
#define FULLM 0xffffffffu

__device__ float g_scores[NROWS];
__device__ int g_hist[BB * 256];   // zero-init; re-zeroed by nms each call

// ---------------------------------------------------------------------------
// Kernel 1: fused head (R11 best config). Per-warp private cp.async pipeline,
// 3-stage ring, no barriers in mainloop. 8 warps x 4 rows; 3 blocks/SM.
// ---------------------------------------------------------------------------
__global__ __launch_bounds__(256, 3) void head_kernel(
    const float* __restrict__ feats, const float* __restrict__ proposals,
    const float* __restrict__ W_cls, const float* __restrict__ b_cls,
    const float* __restrict__ W_box, const float* __restrict__ b_box,
    float* __restrict__ out)
{
    extern __shared__ float sm[];
    float4* wS   = reinterpret_cast<float4*>(sm);   // 6*256 float4 = 24 KB
    float*  fS   = sm + 6 * DD;                     // 8 warps * 1536 floats

    const int tid  = threadIdx.x;
    const int warp = tid >> 5;
    const int lane = tid & 31;
    const int grow0 = blockIdx.x * 32 + warp * 4;   // this warp's first row

    float* wbuf = fS + warp * (3 * 512);            // 3 stages x 512 floats
    const unsigned sb = (unsigned)__cvta_generic_to_shared(wbuf);

    // issue stage st loading column chunk j (cols [j*128, j*128+128))
    auto issue_stage = [&](int st, int j) {
        #pragma unroll
        for (int r = 0; r < 4; r++) {
            const float* gsrc = feats + (size_t)(grow0 + r) * DD + j * 128 + 4 * lane;
            unsigned dst = sb + st * 2048 + r * 512 + 16 * lane;
            asm volatile("cp.async.cg.shared.global [%0], [%1], 16;\n"
                         :: "r"(dst), "l"(gsrc));
        }
        asm volatile("cp.async.commit_group;\n");
    };

    issue_stage(0, 0);
    issue_stage(1, 1);

    // stage weights (block-cooperative): rows 0-1 W_cls, rows 2-5 W_box[4..7]
    for (int i = tid; i < 6 * 256; i += 256) {
        int c = i >> 8, e = i & 255;
        const float* src = (c < 2) ? (W_cls + c * DD) : (W_box + (c + 2) * DD);
        wS[i] = reinterpret_cast<const float4*>(src)[e];
    }
    __syncthreads();

    float acc[4][6];
    #pragma unroll
    for (int r = 0; r < 4; r++)
        #pragma unroll
        for (int c = 0; c < 6; c++) acc[r][c] = 0.f;

    #pragma unroll
    for (int j = 0; j < 8; j++) {
        if (j < 6) {
            issue_stage((j + 2) % 3, j + 2);
            asm volatile("cp.async.wait_group 2;\n");
        } else if (j == 6) {
            asm volatile("cp.async.wait_group 1;\n");
        } else {
            asm volatile("cp.async.wait_group 0;\n");
        }

        const float* fb = wbuf + (j % 3) * 512;
        float4 fr[4];
        #pragma unroll
        for (int r = 0; r < 4; r++)
            fr[r] = *reinterpret_cast<const float4*>(fb + r * 128 + 4 * lane);
        #pragma unroll
        for (int c = 0; c < 6; c++) {
            float4 w = wS[c * 256 + j * 32 + lane];
            #pragma unroll
            for (int r = 0; r < 4; r++)
                acc[r][c] += fr[r].x * w.x + fr[r].y * w.y +
                             fr[r].z * w.z + fr[r].w * w.w;
        }
    }

    #pragma unroll
    for (int r = 0; r < 4; r++)
        #pragma unroll
        for (int c = 0; c < 6; c++)
            #pragma unroll
            for (int s = 16; s > 0; s >>= 1)
                acc[r][c] += __shfl_xor_sync(FULLM, acc[r][c], s);

    if (lane < 4) {
        float v0 = 0.f, v1 = 0.f, v2 = 0.f, v3 = 0.f, v4 = 0.f, v5 = 0.f;
        #pragma unroll
        for (int r = 0; r < 4; r++)
            if (lane == r) {
                v0 = acc[r][0]; v1 = acc[r][1]; v2 = acc[r][2];
                v3 = acc[r][3]; v4 = acc[r][4]; v5 = acc[r][5];
            }
        const int row = grow0 + lane;

        float l0 = v0 + b_cls[0];
        float l1 = v1 + b_cls[1];
        float score = 1.f / (1.f + expf(l0 - l1));

        float dx = (v2 + b_box[4]) / 10.0f;
        float dy = (v3 + b_box[5]) / 10.0f;
        float dw = fminf((v4 + b_box[6]) / 5.0f, CLIPV);
        float dh = fminf((v5 + b_box[7]) / 5.0f, CLIPV);

        float4 p = reinterpret_cast<const float4*>(proposals)[row];
        float w  = p.z - p.x;
        float h  = p.w - p.y;
        float cx = p.x + 0.5f * w;
        float cy = p.y + 0.5f * h;
        float pcx = dx * w + cx;
        float pcy = dy * h + cy;
        float pw  = expf(dw) * w;
        float ph  = expf(dh) * h;

        float x1 = fminf(fmaxf(pcx - 0.5f * pw, 0.f), 800.f);
        float y1 = fminf(fmaxf(pcy - 0.5f * ph, 0.f), 800.f);
        float x2 = fminf(fmaxf(pcx + 0.5f * pw, 0.f), 800.f);
        float y2 = fminf(fmaxf(pcy + 0.5f * ph, 0.f), 800.f);

        float* o = out + (size_t)row * 5;
        o[0] = x1; o[1] = y1; o[2] = x2; o[3] = y2;
        o[4] = 0.f;                       // default: not kept

        if (score > 0.25f) {
            g_scores[row] = score;
            unsigned bits = __float_as_uint(score);
            int bin = min(max((int)((bits - 0x3E800000u) >> 16), 0), 255);
            atomicAdd(&g_hist[(row / NP) * 256 + bin], 1);
        } else {
            g_scores[row] = 0.f;
        }
    }
}

// ---------------------------------------------------------------------------
// Kernel 2: fused NMS, 512 threads (1 key/thread for sort, 1 slot/thread for
// prep, 2 candidates/warp in conflict tests). One block per batch.
// ---------------------------------------------------------------------------
__global__ __launch_bounds__(512) void nms_kernel(float* __restrict__ out)
{
    __shared__ unsigned long long KEY[TK];
    __shared__ float BX1[TK], BY1[TK], BX2[TK], BY2[TK], BAR_[TK], BSC[TK];
    __shared__ int   BIDX[TK];
    __shared__ unsigned MYCOL[TK];
    __shared__ unsigned ALIVE0[NCHUNK];
    __shared__ int   CONF[32];
    __shared__ int   ACC[128];
    __shared__ unsigned tbits_s;
    __shared__ int ccount, npick_s, done_s;

    const int b = blockIdx.x;
    const int t = threadIdx.x;
    float* ob = out + (size_t)b * NP * 5;
    const float4* gs4 = reinterpret_cast<const float4*>(g_scores + b * NP);

    if (t == 0) { ccount = 0; npick_s = 0; done_s = 0; }

    // ---- threshold from histogram (warp 0, register suffix scan) ----
    if (t < 32) {
        int h[8];
        #pragma unroll
        for (int q = 0; q < 8; q++)
            h[q] = g_hist[b * 256 + t * 8 + q];
        #pragma unroll
        for (int q = 6; q >= 0; q--) h[q] += h[q + 1];
        int lanetot = h[0];
        int suf = lanetot;
        #pragma unroll
        for (int s = 1; s < 32; s <<= 1) {
            int o = __shfl_down_sync(FULLM, suf, s);
            if (t + s < 32) suf += o;
        }
        int excl = suf - lanetot;
        unsigned lm = __ballot_sync(FULLM, (h[0] + excl) >= KSEL);
        if (lm == 0u) {
            if (t == 0) tbits_s = 0x3E800000u;
        } else {
            int hl = 31 - __clz(lm);
            if (t == hl) {
                int bq = 0;
                #pragma unroll
                for (int q = 1; q < 8; q++)
                    if (h[q] + excl >= KSEL) bq = q;
                tbits_s = 0x3E800000u + ((unsigned)(t * 8 + bq) << 16);
            }
        }
    }
    __syncthreads();
    const unsigned tbits = tbits_s;

    if (t < 256) g_hist[b * 256 + t] = 0;    // reset for next launch

    // ---- compact candidates (2 float4 per thread) ----
    #pragma unroll
    for (int n4 = t; n4 < NP / 4; n4 += 512) {
        float4 sv = gs4[n4];
        const float* s = &sv.x;
        unsigned bits[4];
        int cnt = 0;
        #pragma unroll
        for (int q = 0; q < 4; q++) {
            bits[q] = __float_as_uint(s[q]);
            if (s[q] > 0.f && bits[q] >= tbits) cnt++;
        }
        if (cnt) {
            int slot = atomicAdd(&ccount, cnt);
            #pragma unroll
            for (int q = 0; q < 4; q++) {
                if (s[q] > 0.f && bits[q] >= tbits && slot < TK) {
                    int n = n4 * 4 + q;
                    KEY[slot++] = ((unsigned long long)bits[q] << 32)
                                | (unsigned long long)(4095 - n);
                }
            }
        }
    }
    __syncthreads();
    const int C = min(ccount, TK);
    if (t >= C) KEY[t] = 0ull;
    __syncthreads();

    // ---- bitonic sort descending, 512 keys, exactly 1 per thread ----
    {
        unsigned long long e = KEY[t];
        #pragma unroll
        for (int k = 2; k <= 32; k <<= 1)
            #pragma unroll
            for (int j = k >> 1; j > 0; j >>= 1) {
                unsigned long long p = __shfl_xor_sync(FULLM, e, j);
                bool mx = ((t & k) == 0) == ((t & j) == 0);
                e = mx ? (e > p ? e : p) : (e < p ? e : p);
            }
        KEY[t] = e;
    }
    __syncthreads();

    for (int k = 64; k <= TK; k <<= 1) {
        for (int j = k >> 1; j >= 32; j >>= 1) {
            int ixj = t ^ j;
            if (ixj > t) {
                unsigned long long a = KEY[t];
                unsigned long long c = KEY[ixj];
                bool swap = ((t & k) == 0) ? (a < c) : (a > c);
                if (swap) { KEY[t] = c; KEY[ixj] = a; }
            }
            __syncthreads();
        }
        {
            unsigned long long e = KEY[t];
            bool dir = ((t & k) == 0);
            #pragma unroll
            for (int j = 16; j > 0; j >>= 1) {
                unsigned long long p = __shfl_xor_sync(FULLM, e, j);
                bool mx = dir == ((t & j) == 0);
                e = mx ? (e > p ? e : p) : (e < p ? e : p);
            }
            KEY[t] = e;
        }
        __syncthreads();
    }

    // ---- parallel candidate prep + intra-chunk pairwise masks ----
    {
        const int w = t >> 5, lane = t & 31;   // w covers all 16 chunks
        const int slot = t;
        unsigned long long key = KEY[slot];
        float sc = __uint_as_float((unsigned)(key >> 32));
        int   idx = 4095 - (int)(key & 0xFFFull);
        float x1 = 0.f, y1 = 0.f, x2 = 0.f, y2 = 0.f;
        if (sc > 0.f) {
            x1 = __ldg(&ob[idx * 5 + 0]); y1 = __ldg(&ob[idx * 5 + 1]);
            x2 = __ldg(&ob[idx * 5 + 2]); y2 = __ldg(&ob[idx * 5 + 3]);
        }
        float ar = fmaxf(x2 - x1, 0.f) * fmaxf(y2 - y1, 0.f);
        BX1[slot] = x1; BY1[slot] = y1;
        BX2[slot] = x2; BY2[slot] = y2;
        BAR_[slot] = ar; BSC[slot] = sc; BIDX[slot] = idx;
        unsigned am = __ballot_sync(FULLM, sc > 0.f);
        if (lane == 0) ALIVE0[w] = am;

        unsigned conf = 0;
        #pragma unroll 4
        for (int j = 0; j < 32; j++) {
            float cx1 = __shfl_sync(FULLM, x1, j);
            float cy1 = __shfl_sync(FULLM, y1, j);
            float cx2 = __shfl_sync(FULLM, x2, j);
            float cy2 = __shfl_sync(FULLM, y2, j);
            float ca  = fmaxf(cx2 - cx1, 0.f) * fmaxf(cy2 - cy1, 0.f);
            float ix1 = fmaxf(cx1, x1);
            float iy1 = fmaxf(cy1, y1);
            float ix2 = fminf(cx2, x2);
            float iy2 = fminf(cy2, y2);
            float inter = fmaxf(ix2 - ix1, 0.f) * fmaxf(iy2 - iy1, 0.f);
            float denom = ca + ar - inter + 1e-9f;
            if (inter > 0.5f * denom) conf |= (1u << j);
        }
        unsigned mycol = 0;
        #pragma unroll
        for (int j = 0; j < 32; j++) {
            unsigned bcol = __ballot_sync(FULLM, (conf >> j) & 1u);
            if (lane == j) mycol = bcol;
        }
        MYCOL[slot] = mycol;
    }
    __syncthreads();

    // ---- chunk loop: block-parallel accepted-test + uniform resolve ----
    for (int chunk = 0; chunk < NCHUNK; chunk++) {
        if (done_s) break;

        // phase 1: warp wi tests candidates 2wi (lanes 0-15) and 2wi+1
        // (lanes 16-31) against the accepted list (strided by 16).
        {
            const int wi = t >> 5;             // 0..15
            const int half = (t >> 4) & 1;     // 0 or 1
            const int l = t & 15;
            const int cslot = chunk * 32 + wi * 2 + half;
            const int np = npick_s;
            float cx1 = BX1[cslot], cy1 = BY1[cslot];
            float cx2 = BX2[cslot], cy2 = BY2[cslot];
            float car = BAR_[cslot];
            bool conflict = false;
            #pragma unroll
            for (int s2 = 0; s2 < 7; s2++) {   // 7*16 = 112 >= 100
                int a = s2 * 16 + l;
                if (a < np) {
                    int jj = ACC[a];
                    float ix1 = fmaxf(BX1[jj], cx1);
                    float iy1 = fmaxf(BY1[jj], cy1);
                    float ix2 = fminf(BX2[jj], cx2);
                    float iy2 = fminf(BY2[jj], cy2);
                    float inter = fmaxf(ix2 - ix1, 0.f) * fmaxf(iy2 - iy1, 0.f);
                    float denom = BAR_[jj] + car - inter + 1e-9f;
                    if (inter > 0.5f * denom) conflict = true;
                }
            }
            unsigned cb = __ballot_sync(FULLM, conflict);
            if ((t & 31) == 0) {
                CONF[wi * 2 + 0] = (cb & 0x0000FFFFu) ? 1 : 0;
                CONF[wi * 2 + 1] = (cb & 0xFFFF0000u) ? 1 : 0;
            }
        }
        __syncthreads();

        // phase 2: warp 0 — uniform bitmask resolve
        if (t < 32) {
            const int lane = t;
            unsigned a0 = ALIVE0[chunk];
            if ((a0 & 1u) == 0u) {
                if (lane == 0) done_s = 1;   // sorted: leader dead => all dead
            } else {
                bool cf = CONF[lane] != 0;
                unsigned alive = a0 & ~__ballot_sync(FULLM, cf);
                int np = npick_s;
                unsigned rem = alive, picked = 0;
                while (rem && np < 100) {
                    int kk = __ffs(rem) - 1;
                    picked |= (1u << kk);
                    np++;
                    unsigned kills = MYCOL[chunk * 32 + kk];
                    rem &= ~kills;
                    rem &= ~(1u << kk);
                }
                if ((picked >> lane) & 1u) {
                    int pos = npick_s + __popc(picked & ((1u << lane) - 1u));
                    int cslot = chunk * 32 + lane;
                    ACC[pos] = cslot;
                    ob[BIDX[cslot] * 5 + 4] = BSC[cslot];
                }
                if (lane == 0) {
                    npick_s = np;
                    if (np >= 100) done_s = 1;
                }
            }
        }
        __syncthreads();
    }
}

extern "C" void kernel_launch(void* const* d_in, const int* in_sizes, int n_in,
                              void* d_out, int out_size)
{
    const float* feats     = (const float*)d_in[0];
    const float* proposals = (const float*)d_in[1];
    const float* W_cls     = (const float*)d_in[2];
    const float* b_cls     = (const float*)d_in[3];
    const float* W_box     = (const float*)d_in[4];
    const float* b_box     = (const float*)d_in[5];
    float* out = (float*)d_out;

    const int head_smem = (6 * DD + 8 * 3 * 512) * (int)sizeof(float); // 72 KB
    cudaFuncSetAttribute(head_kernel,
                         cudaFuncAttributeMaxDynamicSharedMemorySize,
                         head_smem);
    head_kernel<<<NROWS / 32, 256, head_smem>>>(feats, proposals, W_cls, b_cls,
                                                W_box, b_box, out);
    nms_kernel<<<BB, 512>>>(out);
}

// round 15
// speedup vs baseline: 1.0790x; 1.0407x over previous
#include <cuda_runtime.h>

#define BB 16
#define NP 4000
#define TK 256            // sorted candidate capacity (pow2)
#define NCHUNK (TK/32)    // 8
#define KSEL 192          // target top-K for threshold selection
#define DD 1024
#define NROWS (BB*NP)
#define CLIPV 4.135166556742356f   // log(1000/16)
#define FULLM 0xffffffffu

__device__ float g_scores[NROWS];
__device__ int g_hist[BB * 256];   // zero-init; re-zeroed by nms each call

// ---------------------------------------------------------------------------
// Kernel 1: fused head (R11 best config). Per-warp private cp.async pipeline,
// 3-stage ring, no barriers in mainloop. 8 warps x 4 rows; 3 blocks/SM.
// ---------------------------------------------------------------------------
__global__ __launch_bounds__(256, 3) void head_kernel(
    const float* __restrict__ feats, const float* __restrict__ proposals,
    const float* __restrict__ W_cls, const float* __restrict__ b_cls,
    const float* __restrict__ W_box, const float* __restrict__ b_box,
    float* __restrict__ out)
{
    extern __shared__ float sm[];
    float4* wS   = reinterpret_cast<float4*>(sm);   // 6*256 float4 = 24 KB
    float*  fS   = sm + 6 * DD;                     // 8 warps * 1536 floats

    const int tid  = threadIdx.x;
    const int warp = tid >> 5;
    const int lane = tid & 31;
    const int grow0 = blockIdx.x * 32 + warp * 4;   // this warp's first row

    float* wbuf = fS + warp * (3 * 512);            // 3 stages x 512 floats
    const unsigned sb = (unsigned)__cvta_generic_to_shared(wbuf);

    auto issue_stage = [&](int st, int j) {
        #pragma unroll
        for (int r = 0; r < 4; r++) {
            const float* gsrc = feats + (size_t)(grow0 + r) * DD + j * 128 + 4 * lane;
            unsigned dst = sb + st * 2048 + r * 512 + 16 * lane;
            asm volatile("cp.async.cg.shared.global [%0], [%1], 16;\n"
                         :: "r"(dst), "l"(gsrc));
        }
        asm volatile("cp.async.commit_group;\n");
    };

    issue_stage(0, 0);
    issue_stage(1, 1);

    for (int i = tid; i < 6 * 256; i += 256) {
        int c = i >> 8, e = i & 255;
        const float* src = (c < 2) ? (W_cls + c * DD) : (W_box + (c + 2) * DD);
        wS[i] = reinterpret_cast<const float4*>(src)[e];
    }
    __syncthreads();

    float acc[4][6];
    #pragma unroll
    for (int r = 0; r < 4; r++)
        #pragma unroll
        for (int c = 0; c < 6; c++) acc[r][c] = 0.f;

    #pragma unroll
    for (int j = 0; j < 8; j++) {
        if (j < 6) {
            issue_stage((j + 2) % 3, j + 2);
            asm volatile("cp.async.wait_group 2;\n");
        } else if (j == 6) {
            asm volatile("cp.async.wait_group 1;\n");
        } else {
            asm volatile("cp.async.wait_group 0;\n");
        }

        const float* fb = wbuf + (j % 3) * 512;
        float4 fr[4];
        #pragma unroll
        for (int r = 0; r < 4; r++)
            fr[r] = *reinterpret_cast<const float4*>(fb + r * 128 + 4 * lane);
        #pragma unroll
        for (int c = 0; c < 6; c++) {
            float4 w = wS[c * 256 + j * 32 + lane];
            #pragma unroll
            for (int r = 0; r < 4; r++)
                acc[r][c] += fr[r].x * w.x + fr[r].y * w.y +
                             fr[r].z * w.z + fr[r].w * w.w;
        }
    }

    #pragma unroll
    for (int r = 0; r < 4; r++)
        #pragma unroll
        for (int c = 0; c < 6; c++)
            #pragma unroll
            for (int s = 16; s > 0; s >>= 1)
                acc[r][c] += __shfl_xor_sync(FULLM, acc[r][c], s);

    if (lane < 4) {
        float v0 = 0.f, v1 = 0.f, v2 = 0.f, v3 = 0.f, v4 = 0.f, v5 = 0.f;
        #pragma unroll
        for (int r = 0; r < 4; r++)
            if (lane == r) {
                v0 = acc[r][0]; v1 = acc[r][1]; v2 = acc[r][2];
                v3 = acc[r][3]; v4 = acc[r][4]; v5 = acc[r][5];
            }
        const int row = grow0 + lane;

        float l0 = v0 + b_cls[0];
        float l1 = v1 + b_cls[1];
        float score = 1.f / (1.f + expf(l0 - l1));

        float dx = (v2 + b_box[4]) / 10.0f;
        float dy = (v3 + b_box[5]) / 10.0f;
        float dw = fminf((v4 + b_box[6]) / 5.0f, CLIPV);
        float dh = fminf((v5 + b_box[7]) / 5.0f, CLIPV);

        float4 p = reinterpret_cast<const float4*>(proposals)[row];
        float w  = p.z - p.x;
        float h  = p.w - p.y;
        float cx = p.x + 0.5f * w;
        float cy = p.y + 0.5f * h;
        float pcx = dx * w + cx;
        float pcy = dy * h + cy;
        float pw  = expf(dw) * w;
        float ph  = expf(dh) * h;

        float x1 = fminf(fmaxf(pcx - 0.5f * pw, 0.f), 800.f);
        float y1 = fminf(fmaxf(pcy - 0.5f * ph, 0.f), 800.f);
        float x2 = fminf(fmaxf(pcx + 0.5f * pw, 0.f), 800.f);
        float y2 = fminf(fmaxf(pcy + 0.5f * ph, 0.f), 800.f);

        float* o = out + (size_t)row * 5;
        o[0] = x1; o[1] = y1; o[2] = x2; o[3] = y2;
        o[4] = 0.f;                       // default: not kept

        if (score > 0.25f) {
            g_scores[row] = score;
            unsigned bits = __float_as_uint(score);
            int bin = min(max((int)((bits - 0x3E800000u) >> 16), 0), 255);
            atomicAdd(&g_hist[(row / NP) * 256 + bin], 1);
        } else {
            g_scores[row] = 0.f;
        }
    }
}

// ---------------------------------------------------------------------------
// Kernel 2: fused NMS, 512 threads, TK=256 sorted candidates.
// ---------------------------------------------------------------------------
__global__ __launch_bounds__(512) void nms_kernel(float* __restrict__ out)
{
    __shared__ unsigned long long KEY[TK];
    __shared__ float BX1[TK], BY1[TK], BX2[TK], BY2[TK], BAR_[TK], BSC[TK];
    __shared__ int   BIDX[TK];
    __shared__ unsigned MYCOL[TK];
    __shared__ unsigned ALIVE0[NCHUNK];
    __shared__ int   CONF[32];
    __shared__ int   ACC[128];
    __shared__ unsigned tbits_s;
    __shared__ int ccount, npick_s, done_s;

    const int b = blockIdx.x;
    const int t = threadIdx.x;
    float* ob = out + (size_t)b * NP * 5;
    const float4* gs4 = reinterpret_cast<const float4*>(g_scores + b * NP);

    if (t == 0) { ccount = 0; npick_s = 0; done_s = 0; }

    // ---- threshold from histogram (warp 0, register suffix scan) ----
    if (t < 32) {
        int h[8];
        #pragma unroll
        for (int q = 0; q < 8; q++)
            h[q] = g_hist[b * 256 + t * 8 + q];
        #pragma unroll
        for (int q = 6; q >= 0; q--) h[q] += h[q + 1];
        int lanetot = h[0];
        int suf = lanetot;
        #pragma unroll
        for (int s = 1; s < 32; s <<= 1) {
            int o = __shfl_down_sync(FULLM, suf, s);
            if (t + s < 32) suf += o;
        }
        int excl = suf - lanetot;
        unsigned lm = __ballot_sync(FULLM, (h[0] + excl) >= KSEL);
        if (lm == 0u) {
            if (t == 0) tbits_s = 0x3E800000u;
        } else {
            int hl = 31 - __clz(lm);
            if (t == hl) {
                int bq = 0;
                #pragma unroll
                for (int q = 1; q < 8; q++)
                    if (h[q] + excl >= KSEL) bq = q;
                tbits_s = 0x3E800000u + ((unsigned)(t * 8 + bq) << 16);
            }
        }
    }
    __syncthreads();
    const unsigned tbits = tbits_s;

    if (t < 256) g_hist[b * 256 + t] = 0;    // reset for next launch

    // ---- compact candidates ----
    #pragma unroll
    for (int n4 = t; n4 < NP / 4; n4 += 512) {
        float4 sv = gs4[n4];
        const float* s = &sv.x;
        unsigned bits[4];
        int cnt = 0;
        #pragma unroll
        for (int q = 0; q < 4; q++) {
            bits[q] = __float_as_uint(s[q]);
            if (s[q] > 0.f && bits[q] >= tbits) cnt++;
        }
        if (cnt) {
            int slot = atomicAdd(&ccount, cnt);
            #pragma unroll
            for (int q = 0; q < 4; q++) {
                if (s[q] > 0.f && bits[q] >= tbits && slot < TK) {
                    int n = n4 * 4 + q;
                    KEY[slot++] = ((unsigned long long)bits[q] << 32)
                                | (unsigned long long)(4095 - n);
                }
            }
        }
    }
    __syncthreads();
    const int C = min(ccount, TK);
    if (t >= C && t < TK) KEY[t] = 0ull;
    __syncthreads();

    // ---- bitonic sort descending, 256 keys, 1 per thread (t < 256) ----
    if (t < TK) {
        unsigned long long e = KEY[t];
        #pragma unroll
        for (int k = 2; k <= 32; k <<= 1)
            #pragma unroll
            for (int j = k >> 1; j > 0; j >>= 1) {
                unsigned long long p = __shfl_xor_sync(FULLM, e, j);
                bool mx = ((t & k) == 0) == ((t & j) == 0);
                e = mx ? (e > p ? e : p) : (e < p ? e : p);
            }
        KEY[t] = e;
    }
    __syncthreads();

    for (int k = 64; k <= TK; k <<= 1) {
        for (int j = k >> 1; j >= 32; j >>= 1) {
            if (t < TK) {
                int ixj = t ^ j;
                if (ixj > t) {
                    unsigned long long a = KEY[t];
                    unsigned long long c = KEY[ixj];
                    bool swap = ((t & k) == 0) ? (a < c) : (a > c);
                    if (swap) { KEY[t] = c; KEY[ixj] = a; }
                }
            }
            __syncthreads();
        }
        if (t < TK) {
            unsigned long long e = KEY[t];
            bool dir = ((t & k) == 0);
            #pragma unroll
            for (int j = 16; j > 0; j >>= 1) {
                unsigned long long p = __shfl_xor_sync(FULLM, e, j);
                bool mx = dir == ((t & j) == 0);
                e = mx ? (e > p ? e : p) : (e < p ? e : p);
            }
            KEY[t] = e;
        }
        __syncthreads();
    }

    // ---- parallel candidate prep + intra-chunk pairwise masks (t < 256) ----
    if (t < TK) {
        const int w = t >> 5, lane = t & 31;   // w covers all 8 chunks
        const int slot = t;
        unsigned long long key = KEY[slot];
        float sc = __uint_as_float((unsigned)(key >> 32));
        int   idx = 4095 - (int)(key & 0xFFFull);
        float x1 = 0.f, y1 = 0.f, x2 = 0.f, y2 = 0.f;
        if (sc > 0.f) {
            x1 = __ldg(&ob[idx * 5 + 0]); y1 = __ldg(&ob[idx * 5 + 1]);
            x2 = __ldg(&ob[idx * 5 + 2]); y2 = __ldg(&ob[idx * 5 + 3]);
        }
        float ar = fmaxf(x2 - x1, 0.f) * fmaxf(y2 - y1, 0.f);
        BX1[slot] = x1; BY1[slot] = y1;
        BX2[slot] = x2; BY2[slot] = y2;
        BAR_[slot] = ar; BSC[slot] = sc; BIDX[slot] = idx;
        unsigned am = __ballot_sync(FULLM, sc > 0.f);
        if (lane == 0) ALIVE0[w] = am;

        unsigned conf = 0;
        #pragma unroll 4
        for (int j = 0; j < 32; j++) {
            float cx1 = __shfl_sync(FULLM, x1, j);
            float cy1 = __shfl_sync(FULLM, y1, j);
            float cx2 = __shfl_sync(FULLM, x2, j);
            float cy2 = __shfl_sync(FULLM, y2, j);
            float ca  = fmaxf(cx2 - cx1, 0.f) * fmaxf(cy2 - cy1, 0.f);
            float ix1 = fmaxf(cx1, x1);
            float iy1 = fmaxf(cy1, y1);
            float ix2 = fminf(cx2, x2);
            float iy2 = fminf(cy2, y2);
            float inter = fmaxf(ix2 - ix1, 0.f) * fmaxf(iy2 - iy1, 0.f);
            float denom = ca + ar - inter + 1e-9f;
            if (inter > 0.5f * denom) conf |= (1u << j);
        }
        unsigned mycol = 0;
        #pragma unroll
        for (int j = 0; j < 32; j++) {
            unsigned bcol = __ballot_sync(FULLM, (conf >> j) & 1u);
            if (lane == j) mycol = bcol;
        }
        MYCOL[slot] = mycol;
    }
    __syncthreads();

    // ---- chunk loop: block-parallel accepted-test + uniform resolve ----
    for (int chunk = 0; chunk < NCHUNK; chunk++) {
        if (done_s) break;

        // phase 1: warp wi tests candidates 2wi (lanes 0-15) and 2wi+1
        // (lanes 16-31) against the accepted list (strided by 16).
        {
            const int wi = t >> 5;             // 0..15
            const int half = (t >> 4) & 1;     // 0 or 1
            const int l = t & 15;
            const int cslot = chunk * 32 + wi * 2 + half;
            const int np = npick_s;
            float cx1 = BX1[cslot], cy1 = BY1[cslot];
            float cx2 = BX2[cslot], cy2 = BY2[cslot];
            float car = BAR_[cslot];
            bool conflict = false;
            #pragma unroll
            for (int s2 = 0; s2 < 7; s2++) {   // 7*16 = 112 >= 100
                int a = s2 * 16 + l;
                if (a < np) {
                    int jj = ACC[a];
                    float ix1 = fmaxf(BX1[jj], cx1);
                    float iy1 = fmaxf(BY1[jj], cy1);
                    float ix2 = fminf(BX2[jj], cx2);
                    float iy2 = fminf(BY2[jj], cy2);
                    float inter = fmaxf(ix2 - ix1, 0.f) * fmaxf(iy2 - iy1, 0.f);
                    float denom = BAR_[jj] + car - inter + 1e-9f;
                    if (inter > 0.5f * denom) conflict = true;
                }
            }
            unsigned cb = __ballot_sync(FULLM, conflict);
            if ((t & 31) == 0) {
                CONF[wi * 2 + 0] = (cb & 0x0000FFFFu) ? 1 : 0;
                CONF[wi * 2 + 1] = (cb & 0xFFFF0000u) ? 1 : 0;
            }
        }
        __syncthreads();

        // phase 2: warp 0 — uniform bitmask resolve
        if (t < 32) {
            const int lane = t;
            unsigned a0 = ALIVE0[chunk];
            if ((a0 & 1u) == 0u) {
                if (lane == 0) done_s = 1;   // sorted: leader dead => all dead
            } else {
                bool cf = CONF[lane] != 0;
                unsigned alive = a0 & ~__ballot_sync(FULLM, cf);
                int np = npick_s;
                unsigned rem = alive, picked = 0;
                while (rem && np < 100) {
                    int kk = __ffs(rem) - 1;
                    picked |= (1u << kk);
                    np++;
                    unsigned kills = MYCOL[chunk * 32 + kk];
                    rem &= ~kills;
                    rem &= ~(1u << kk);
                }
                if ((picked >> lane) & 1u) {
                    int pos = npick_s + __popc(picked & ((1u << lane) - 1u));
                    int cslot = chunk * 32 + lane;
                    ACC[pos] = cslot;
                    ob[BIDX[cslot] * 5 + 4] = BSC[cslot];
                }
                if (lane == 0) {
                    npick_s = np;
                    if (np >= 100) done_s = 1;
                }
            }
        }
        __syncthreads();
    }
}

extern "C" void kernel_launch(void* const* d_in, const int* in_sizes, int n_in,
                              void* d_out, int out_size)
{
    const float* feats     = (const float*)d_in[0];
    const float* proposals = (const float*)d_in[1];
    const float* W_cls     = (const float*)d_in[2];
    const float* b_cls     = (const float*)d_in[3];
    const float* W_box     = (const float*)d_in[4];
    const float* b_box     = (const float*)d_in[5];
    float* out = (float*)d_out;

    const int head_smem = (6 * DD + 8 * 3 * 512) * (int)sizeof(float); // 72 KB
    cudaFuncSetAttribute(head_kernel,
                         cudaFuncAttributeMaxDynamicSharedMemorySize,
                         head_smem);
    head_kernel<<<NROWS / 32, 256, head_smem>>>(feats, proposals, W_cls, b_cls,
                                                W_box, b_box, out);
    nms_kernel<<<BB, 512>>>(out);
}